// round 2
// baseline (speedup 1.0000x reference)
#include <cuda_runtime.h>
#include <math.h>

#define DIMV 32
#define KN 16
#define NREL 60
#define NTHREADS 256

__device__ __forceinline__ float warp_max(float v) {
    #pragma unroll
    for (int o = 16; o > 0; o >>= 1) v = fmaxf(v, __shfl_xor_sync(0xffffffffu, v, o));
    return v;
}
__device__ __forceinline__ float warp_sum(float v) {
    #pragma unroll
    for (int o = 16; o > 0; o >>= 1) v += __shfl_xor_sync(0xffffffffu, v, o);
    return v;
}
__device__ __forceinline__ float sigmoidf_(float x) { return 1.f / (1.f + expf(-x)); }

__global__ __launch_bounds__(NTHREADS) void mkgcn_kernel(
    const int*   __restrict__ users,
    const int*   __restrict__ items,
    const float* __restrict__ entity_emb,
    const float* __restrict__ relation_emb,
    const int*   __restrict__ adj_entity,
    const int*   __restrict__ adj_relation,
    const int*   __restrict__ user_history,
    const float* __restrict__ W,
    const float* __restrict__ bvec,
    float*       __restrict__ out)
{
    __shared__ float Ws[DIMV * DIMV];
    __shared__ float bs[DIMV];
    __shared__ float rels[NREL * DIMV];
    __shared__ float udotr[NREL];
    __shared__ float uemb[DIMV];
    __shared__ float upart[8][DIMV];
    __shared__ float e0s[DIMV];
    __shared__ float e1s[KN * DIMV];
    __shared__ float t1s[KN * DIMV];
    __shared__ int   e1id[KN];
    __shared__ int   r0id[KN];
    __shared__ int   e2id[KN * KN];
    __shared__ int   r1id[KN * KN];
    __shared__ float attnbuf[8][KN];
    __shared__ float attn0[KN];

    const int tid  = threadIdx.x;
    const int w    = tid >> 5;
    const int lane = tid & 31;
    const int bidx = blockIdx.x;

    const int uid  = __ldg(&users[bidx]);
    const int item = __ldg(&items[bidx]);

    // Stage W, b, relation table into shared
    #pragma unroll 4
    for (int i = tid; i < DIMV * DIMV; i += NTHREADS) Ws[i] = __ldg(&W[i]);
    if (tid < DIMV) bs[tid] = __ldg(&bvec[tid]);
    for (int i = tid; i < NREL * DIMV; i += NTHREADS) rels[i] = __ldg(&relation_emb[i]);

    // Hop-1 adjacency of the item
    if (tid < KN) {
        e1id[tid] = __ldg(&adj_entity[item * KN + tid]);
        r0id[tid] = __ldg(&adj_relation[item * KN + tid]);
    }

    // User embedding partials: each warp gathers 2 history vectors
    {
        const int* hrow = user_history + uid * KN;
        float acc = 0.f;
        #pragma unroll
        for (int t = 0; t < 2; ++t) {
            int h  = w + t * 8;
            int id = __ldg(&hrow[h]);
            acc += __ldg(&entity_emb[id * DIMV + lane]);
        }
        upart[w][lane] = acc;
    }
    __syncthreads();

    // Hop-2 adjacency: 256 ids, one per thread (row-coalesced in groups of 16)
    {
        int n = tid >> 4, k = tid & 15;
        int base = e1id[n] * KN + k;
        e2id[tid] = __ldg(&adj_entity[base]);
        r1id[tid] = __ldg(&adj_relation[base]);
    }
    // e1 vectors (16 x 32) and e0 vector into shared
    #pragma unroll 2
    for (int i = tid; i < KN * DIMV; i += NTHREADS)
        e1s[i] = __ldg(&entity_emb[e1id[i >> 5] * DIMV + (i & 31)]);
    if (tid < DIMV) e0s[tid] = __ldg(&entity_emb[item * DIMV + tid]);

    // Reduce user embedding (warp 0)
    if (tid < DIMV) {
        float s = 0.f;
        #pragma unroll
        for (int p = 0; p < 8; ++p) s += upart[p][tid];
        uemb[tid] = s * (1.f / 16.f);
    }
    __syncthreads();

    // udotr[r] = dot(user_emb, relation_emb[r]) for all 60 relations
    for (int r = w; r < NREL; r += 8) {
        float p = uemb[lane] * rels[r * DIMV + lane];
        p = warp_sum(p);
        if (lane == 0) udotr[r] = p;
    }
    __syncthreads();

    // it=0, h=1: 16 nodes, 2 per warp. attn over hop-2 rel ids, gather hop-2
    // entity vectors straight from global, matvec with W, sigmoid.
    for (int n = w; n < KN; n += 8) {
        float sc = (lane < KN) ? udotr[r1id[n * KN + lane]] : -INFINITY;
        float m  = warp_max(sc);
        float e  = (lane < KN) ? expf(sc - m) : 0.f;
        float ss = warp_sum(e);
        if (lane < KN) attnbuf[w][lane] = e / ss;
        __syncwarp();

        float acc = 0.f;
        #pragma unroll
        for (int k = 0; k < KN; ++k)
            acc += attnbuf[w][k] * __ldg(&entity_emb[e2id[n * KN + k] * DIMV + lane]);

        float x = e1s[n * DIMV + lane] + acc;
        float y = bs[lane];
        #pragma unroll
        for (int j = 0; j < DIMV; ++j)
            y += __shfl_sync(0xffffffffu, x, j) * Ws[j * DIMV + lane];
        t1s[n * DIMV + lane] = sigmoidf_(y);
        __syncwarp();
    }
    __syncthreads();

    // it=0 h=0 and it=1 h=0 (same attention weights), warp 0 only
    if (w == 0) {
        float sc = (lane < KN) ? udotr[r0id[lane]] : -INFINITY;
        float m  = warp_max(sc);
        float e  = (lane < KN) ? expf(sc - m) : 0.f;
        float ss = warp_sum(e);
        if (lane < KN) attn0[lane] = e / ss;
        __syncwarp();

        // t0 = sigmoid((e0 + sum_k attn0[k]*e1[k]) @ W + b)
        float acc = 0.f;
        #pragma unroll
        for (int k = 0; k < KN; ++k) acc += attn0[k] * e1s[k * DIMV + lane];
        float x0 = e0s[lane] + acc;
        float y0 = bs[lane];
        #pragma unroll
        for (int j = 0; j < DIMV; ++j)
            y0 += __shfl_sync(0xffffffffu, x0, j) * Ws[j * DIMV + lane];
        float t0 = sigmoidf_(y0);

        // final = tanh((t0 + sum_k attn0[k]*t1[k]) @ W + b)
        float acc2 = 0.f;
        #pragma unroll
        for (int k = 0; k < KN; ++k) acc2 += attn0[k] * t1s[k * DIMV + lane];
        float xf = t0 + acc2;
        float yf = bs[lane];
        #pragma unroll
        for (int j = 0; j < DIMV; ++j)
            yf += __shfl_sync(0xffffffffu, xf, j) * Ws[j * DIMV + lane];
        float f = tanhf(yf);

        // score = sigmoid(dot(user_emb, final))
        float s = warp_sum(uemb[lane] * f);
        if (lane == 0) out[bidx] = sigmoidf_(s);
    }
}

extern "C" void kernel_launch(void* const* d_in, const int* in_sizes, int n_in,
                              void* d_out, int out_size) {
    const int*   users        = (const int*)  d_in[0];
    const int*   items        = (const int*)  d_in[1];
    const float* entity_emb   = (const float*)d_in[2];
    const float* relation_emb = (const float*)d_in[3];
    const int*   adj_entity   = (const int*)  d_in[4];
    const int*   adj_relation = (const int*)  d_in[5];
    const int*   user_history = (const int*)  d_in[6];
    const float* W            = (const float*)d_in[7];
    const float* b            = (const float*)d_in[8];
    float* out = (float*)d_out;

    int B = in_sizes[0];
    mkgcn_kernel<<<B, NTHREADS>>>(users, items, entity_emb, relation_emb,
                                  adj_entity, adj_relation, user_history,
                                  W, b, out);
}

// round 3
// speedup vs baseline: 1.2474x; 1.2474x over previous
#include <cuda_runtime.h>
#include <math.h>

#define DIMV 32
#define KN 16
#define NREL 60
#define NT 256

__device__ __forceinline__ float wmax(float v) {
    #pragma unroll
    for (int o = 16; o > 0; o >>= 1) v = fmaxf(v, __shfl_xor_sync(0xffffffffu, v, o));
    return v;
}
__device__ __forceinline__ float wsum(float v) {
    #pragma unroll
    for (int o = 16; o > 0; o >>= 1) v += __shfl_xor_sync(0xffffffffu, v, o);
    return v;
}
__device__ __forceinline__ float sigm(float x) { return 1.f / (1.f + __expf(-x)); }

__global__ __launch_bounds__(NT, 6) void mkgcn_kernel(
    const int*   __restrict__ users,
    const int*   __restrict__ items,
    const float* __restrict__ emb,
    const float* __restrict__ rel,
    const int*   __restrict__ adjE,
    const int*   __restrict__ adjR,
    const int*   __restrict__ hist,
    const float* __restrict__ W,
    const float* __restrict__ bvec,
    float*       __restrict__ out)
{
    __shared__ __align__(16) float Ws[DIMV * DIMV];
    __shared__ float bs[DIMV];
    __shared__ float uemb[DIMV];
    __shared__ float udotr[64];
    __shared__ __align__(16) float upart[KN][DIMV];
    __shared__ __align__(16) float e0s[DIMV];
    __shared__ __align__(16) float e1s[KN * DIMV];
    __shared__ float t1s[KN * DIMV];
    __shared__ int   e1id[KN], r0id[KN];
    __shared__ int   e2id[KN * KN];
    __shared__ int   r1id[KN * KN];
    __shared__ __align__(16) float xb[8][2][DIMV];
    __shared__ float attn0[KN];

    const int tid  = threadIdx.x;
    const int w    = tid >> 5;
    const int lane = tid & 31;
    const int bidx = blockIdx.x;

    const int uid  = __ldg(&users[bidx]);
    const int item = __ldg(&items[bidx]);

    // ---- Phase A: all independent global loads, maximum overlap ----
    if (tid < KN) {
        e1id[tid] = __ldg(&adjE[item * KN + tid]);
        r0id[tid] = __ldg(&adjR[item * KN + tid]);
    }
    if (tid < DIMV) bs[tid] = __ldg(&bvec[tid]);

    if (tid < 128) {
        // user history gather: 16 rows x 8 float4 groups
        int r = tid >> 3, c = tid & 7;
        int id = __ldg(&hist[uid * KN + r]);
        float4 v = __ldg((const float4*)(emb + (size_t)id * DIMV + c * 4));
        *(float4*)&upart[r][c * 4] = v;
    } else {
        // W staging: 256 float4, 128 threads x 2
        const float4* W4 = (const float4*)W;
        int j = tid - 128;
        ((float4*)Ws)[j]       = __ldg(&W4[j]);
        ((float4*)Ws)[j + 128] = __ldg(&W4[j + 128]);
        if (tid >= 248) {
            int c = tid - 248;
            float4 v = __ldg((const float4*)(emb + (size_t)item * DIMV + c * 4));
            *(float4*)&e0s[c * 4] = v;
        }
    }
    __syncthreads();

    // ---- Phase B: hop-2 adjacency + e1 vectors + user emb reduce ----
    {
        int n = tid >> 4, k = tid & 15;
        int base = e1id[n] * KN + k;
        e2id[tid] = __ldg(&adjE[base]);
        r1id[tid] = __ldg(&adjR[base]);
    }
    if (tid < 128) {
        int r = tid >> 3, c = tid & 7;
        float4 v = __ldg((const float4*)(emb + (size_t)e1id[r] * DIMV + c * 4));
        *(float4*)&e1s[r * DIMV + c * 4] = v;
    }
    if (tid < DIMV) {
        float s = 0.f;
        #pragma unroll
        for (int r = 0; r < KN; ++r) s += upart[r][tid];
        uemb[tid] = s * (1.f / 16.f);
    }
    __syncthreads();

    // ---- Phase C: udotr[r] = dot(uemb, rel[r]) for 60 relations ----
    {
        float ul = uemb[lane];
        for (int r = w; r < NREL; r += 8) {
            float p = wsum(ul * __ldg(&rel[r * DIMV + lane]));
            if (lane == 0) udotr[r] = p;
        }
    }
    __syncthreads();

    // ---- Phase D: hop-1 update. warp w handles nodes w and w+8 ----
    {
        const int n0 = w, n1 = w + 8;
        float a0 = -INFINITY, a1 = -INFINITY;
        if (lane < KN) {
            a0 = udotr[r1id[n0 * KN + lane]];
            a1 = udotr[r1id[n1 * KN + lane]];
        }
        float m0 = wmax(a0), m1 = wmax(a1);
        float p0 = (lane < KN) ? __expf(a0 - m0) : 0.f;
        float p1 = (lane < KN) ? __expf(a1 - m1) : 0.f;
        float at0 = p0 / wsum(p0);
        float at1 = p1 / wsum(p1);

        // gather 2x16 rows with float4 lanes: lane = r*8 + c
        const int c = lane & 7, r = lane >> 3;
        float4 acc0 = make_float4(0.f, 0.f, 0.f, 0.f);
        float4 acc1 = make_float4(0.f, 0.f, 0.f, 0.f);
        #pragma unroll
        for (int p = 0; p < 4; ++p) {
            int k = p * 4 + r;
            float w0 = __shfl_sync(0xffffffffu, at0, k);
            float w1 = __shfl_sync(0xffffffffu, at1, k);
            float4 v0 = __ldg((const float4*)(emb + (size_t)e2id[n0 * KN + k] * DIMV + c * 4));
            float4 v1 = __ldg((const float4*)(emb + (size_t)e2id[n1 * KN + k] * DIMV + c * 4));
            acc0.x += w0 * v0.x; acc0.y += w0 * v0.y; acc0.z += w0 * v0.z; acc0.w += w0 * v0.w;
            acc1.x += w1 * v1.x; acc1.y += w1 * v1.y; acc1.z += w1 * v1.z; acc1.w += w1 * v1.w;
        }
        // reduce over the 4 row-groups (lanes differing in bits 3,4)
        #pragma unroll
        for (int o = 8; o <= 16; o <<= 1) {
            acc0.x += __shfl_xor_sync(0xffffffffu, acc0.x, o);
            acc0.y += __shfl_xor_sync(0xffffffffu, acc0.y, o);
            acc0.z += __shfl_xor_sync(0xffffffffu, acc0.z, o);
            acc0.w += __shfl_xor_sync(0xffffffffu, acc0.w, o);
            acc1.x += __shfl_xor_sync(0xffffffffu, acc1.x, o);
            acc1.y += __shfl_xor_sync(0xffffffffu, acc1.y, o);
            acc1.z += __shfl_xor_sync(0xffffffffu, acc1.z, o);
            acc1.w += __shfl_xor_sync(0xffffffffu, acc1.w, o);
        }
        if (r == 0) {
            *(float4*)&xb[w][0][c * 4] = acc0;
            *(float4*)&xb[w][1][c * 4] = acc1;
        }
        __syncwarp();
        float x0 = xb[w][0][lane] + e1s[n0 * DIMV + lane];
        float x1 = xb[w][1][lane] + e1s[n1 * DIMV + lane];
        float y0 = bs[lane], y1 = bs[lane];
        #pragma unroll
        for (int j = 0; j < DIMV; ++j) {
            float wj = Ws[j * DIMV + lane];
            y0 += __shfl_sync(0xffffffffu, x0, j) * wj;
            y1 += __shfl_sync(0xffffffffu, x1, j) * wj;
        }
        t1s[n0 * DIMV + lane] = sigm(y0);
        t1s[n1 * DIMV + lane] = sigm(y1);
    }
    __syncthreads();

    // ---- Phase E: hop-0 (both iterations share attn0) + score; warp 0 ----
    if (w == 0) {
        float sc = (lane < KN) ? udotr[r0id[lane]] : -INFINITY;
        float m  = wmax(sc);
        float e  = (lane < KN) ? __expf(sc - m) : 0.f;
        float ss = wsum(e);
        float a  = e / ss;
        if (lane < KN) attn0[lane] = a;
        __syncwarp();

        float acc = 0.f;
        #pragma unroll
        for (int k = 0; k < KN; ++k) acc += attn0[k] * e1s[k * DIMV + lane];
        float x0 = e0s[lane] + acc;
        float y0 = bs[lane];
        #pragma unroll
        for (int j = 0; j < DIMV; ++j)
            y0 += __shfl_sync(0xffffffffu, x0, j) * Ws[j * DIMV + lane];
        float t0 = sigm(y0);

        float acc2 = 0.f;
        #pragma unroll
        for (int k = 0; k < KN; ++k) acc2 += attn0[k] * t1s[k * DIMV + lane];
        float xf = t0 + acc2;
        float yf = bs[lane];
        #pragma unroll
        for (int j = 0; j < DIMV; ++j)
            yf += __shfl_sync(0xffffffffu, xf, j) * Ws[j * DIMV + lane];
        float f = tanhf(yf);

        float s = wsum(uemb[lane] * f);
        if (lane == 0) out[bidx] = sigm(s);
    }
}

extern "C" void kernel_launch(void* const* d_in, const int* in_sizes, int n_in,
                              void* d_out, int out_size) {
    const int*   users        = (const int*)  d_in[0];
    const int*   items        = (const int*)  d_in[1];
    const float* entity_emb   = (const float*)d_in[2];
    const float* relation_emb = (const float*)d_in[3];
    const int*   adj_entity   = (const int*)  d_in[4];
    const int*   adj_relation = (const int*)  d_in[5];
    const int*   user_history = (const int*)  d_in[6];
    const float* W            = (const float*)d_in[7];
    const float* b            = (const float*)d_in[8];
    float* out = (float*)d_out;

    int B = in_sizes[0];
    mkgcn_kernel<<<B, NT>>>(users, items, entity_emb, relation_emb,
                            adj_entity, adj_relation, user_history,
                            W, b, out);
}